// round 2
// baseline (speedup 1.0000x reference)
#include <cuda_runtime.h>
#include <cuda_bf16.h>

#ifndef F_DIM
#define F_DIM 16
#endif

// One thread per (edge, feature-quad). quad = tid & 3, edge = tid >> 2.
// Consecutive threads read consecutive float4s of edge_w -> fully coalesced.
// 4 threads of a quad-group share the same src index (broadcast load).
// Scatter via vector reduction atomic (sm_90+): RED.E.ADD.F32 x4, destinations
// are 6.4 MB -> fully L2 resident.
__global__ void __launch_bounds__(256)
spmm_scatter_kernel(const int* __restrict__ src,
                    const float4* __restrict__ edge_w4,  // [E*4] float4
                    float4* __restrict__ out4,           // [N*4] float4
                    int E)
{
    long long tid = (long long)blockIdx.x * blockDim.x + threadIdx.x;
    long long total = (long long)E * 4;
    if (tid >= total) return;

    int e = (int)(tid >> 2);
    int q = (int)(tid & 3);

    int s = src[e];                      // broadcast among 4 lanes
    float4 v = edge_w4[tid];             // coalesced 128B lines

    atomicAdd(&out4[(long long)s * 4 + q], v);
}

extern "C" void kernel_launch(void* const* d_in, const int* in_sizes, int n_in,
                              void* d_out, int out_size)
{
    const int E = 3200000;

    // metadata order: edge [2, E] int32, edge_w [E, 16] f32, then scalars.
    const int*   edge   = (const int*)d_in[0];      // edge[0] = src row, first E ints
    const float* edge_w = (const float*)d_in[1];

    // d_out poisoned to 0xAA -> zero it first (memset node is graph-capturable).
    cudaMemsetAsync(d_out, 0, (size_t)out_size * sizeof(float), 0);

    long long total = (long long)E * 4;
    int threads = 256;
    int blocks = (int)((total + threads - 1) / threads);

    spmm_scatter_kernel<<<blocks, threads>>>(
        edge,                         // src = edge[0], contiguous first E entries
        (const float4*)edge_w,
        (float4*)d_out,
        E);
}